// round 16
// baseline (speedup 1.0000x reference)
#include <cuda_runtime.h>
#include <math.h>

#define G3 32768
#define NVIEW 8

typedef unsigned long long ull;

__device__ __forceinline__ float elu_f(float x)  { return x > 0.f ? x : (__expf(x) - 1.f); }
__device__ __forceinline__ float sigm_f(float x) { return 1.f / (1.f + __expf(-x)); }

__device__ __forceinline__ ull pk2(float lo, float hi) {
    ull r; asm("mov.b64 %0, {%1, %2};" : "=l"(r) : "f"(lo), "f"(hi)); return r;
}
__device__ __forceinline__ float2 upk2(ull a) {
    float lo, hi; asm("mov.b64 {%0, %1}, %2;" : "=f"(lo), "=f"(hi) : "l"(a));
    return make_float2(lo, hi);
}
__device__ __forceinline__ ull fma2(ull a, ull b, ull c) {
    ull d; asm("fma.rn.f32x2 %0, %1, %2, %3;" : "=l"(d) : "l"(a), "l"(b), "l"(c)); return d;
}
__device__ __forceinline__ ull mul2(ull a, ull b) {
    ull d; asm("mul.rn.f32x2 %0, %1, %2;" : "=l"(d) : "l"(a), "l"(b)); return d;
}
__device__ __forceinline__ ull add2(ull a, ull b) {
    ull d; asm("add.rn.f32x2 %0, %1, %2;" : "=l"(d) : "l"(a), "l"(b)); return d;
}
__device__ __forceinline__ float hsum2(ull a) { float2 f = upk2(a); return f.x + f.y; }

// Packed dot, 2 accumulator chains (the validated champion form).
template<int NP>
__device__ __forceinline__ float pdot(const float* __restrict__ wr, const ull* __restrict__ xp) {
    ull a0 = 0ull, a1 = 0ull;
    #pragma unroll
    for (int k = 0; k < NP / 2; ++k) {
        const ulonglong2 w = *reinterpret_cast<const ulonglong2*>(wr + 4 * k);
        a0 = fma2(w.x, xp[2 * k], a0);
        a1 = fma2(w.y, xp[2 * k + 1], a1);
    }
    return hsum2(add2(a0, a1));
}

__global__ __launch_bounds__(128)
void ibr_agg_v11_kernel(
    const float* __restrict__ features,   // (B,N,32,G3)
    const float* __restrict__ mask,       // (B,N,1,G3)
    const float* __restrict__ depth,      // (B,N,1,G3)
    const float* __restrict__ vdir,       // (B,N,3,G3)
    const float* __restrict__ g_rw1, const float* __restrict__ g_rb1,   // (16,4),(16)
    const float* __restrict__ g_rw2, const float* __restrict__ g_rb2,   // (32,16),(32)
    const float* __restrict__ g_bw1, const float* __restrict__ g_bb1,   // (64,96),(64)
    const float* __restrict__ g_bw2, const float* __restrict__ g_bb2,   // (32,64),(32)
    const float* __restrict__ g_vw1, const float* __restrict__ g_vb1,   // (32,32),(32)
    const float* __restrict__ g_vw2, const float* __restrict__ g_vb2,   // (33,32),(33)
    const float* __restrict__ g_v2w1, const float* __restrict__ g_v2b1, // (32,32),(32)
    const float* __restrict__ g_v2w2, const float* __restrict__ g_v2b2, // (1,32),(1)
    const float* __restrict__ g_sw,  const float* __restrict__ g_sb,    // (32,65),(32)
    float* __restrict__ out)              // (B,32,G3)
{
    __shared__ __align__(16) float s_rw1[16 * 4];
    __shared__ __align__(16) float s_rb1[16];
    __shared__ __align__(16) float s_rw2[32 * 16];
    __shared__ __align__(16) float s_rb2[32];
    __shared__ __align__(16) float s_bw1f[64 * 32];   // base_w1 cols 64..95 (feat part)
    __shared__ __align__(16) float s_bw2[32 * 64];
    __shared__ __align__(16) float s_bb2[32];
    __shared__ __align__(16) float s_vw1[32 * 32];
    __shared__ __align__(16) float s_vb1[32];
    __shared__ __align__(16) float s_vw2[33 * 32];
    __shared__ __align__(16) float s_vb2[36];
    __shared__ __align__(16) float s_v2w1[32 * 32];
    __shared__ __align__(16) float s_v2b1[32];
    __shared__ __align__(16) float s_v2w2[32];
    __shared__ __align__(16) float s_sw[32 * 68];     // stat_w rows padded 65->68
    __shared__ __align__(16) float s_sb[32];

    const int tid = threadIdx.x;

    for (int i = tid; i < 16 * 4;  i += 128) s_rw1[i] = g_rw1[i];
    if (tid < 16) s_rb1[tid] = g_rb1[tid];
    for (int i = tid; i < 32 * 16; i += 128) s_rw2[i] = g_rw2[i];
    if (tid < 32) s_rb2[tid] = g_rb2[tid];
    for (int i = tid; i < 64 * 32; i += 128) { int o = i >> 5, c = i & 31; s_bw1f[i] = g_bw1[o * 96 + 64 + c]; }
    for (int i = tid; i < 32 * 64; i += 128) s_bw2[i] = g_bw2[i];
    if (tid < 32) s_bb2[tid] = g_bb2[tid];
    for (int i = tid; i < 32 * 32; i += 128) s_vw1[i] = g_vw1[i];
    if (tid < 32) s_vb1[tid] = g_vb1[tid];
    for (int i = tid; i < 33 * 32; i += 128) s_vw2[i] = g_vw2[i];
    if (tid < 33) s_vb2[tid] = g_vb2[tid];
    for (int i = tid; i < 32 * 32; i += 128) s_v2w1[i] = g_v2w1[i];
    if (tid < 32) s_v2b1[tid] = g_v2b1[tid];
    if (tid < 32) s_v2w2[tid] = g_v2w2[tid];
    for (int i = tid; i < 32 * 65; i += 128) { int o = i / 65, c = i % 65; s_sw[o * 68 + c] = g_sw[i]; }
    if (tid < 32) s_sb[tid] = g_sb[tid];
    __syncthreads();

    const float EPS  = 1e-8f;
    const float v2b2 = __ldg(g_v2b2);

    const int gv = blockIdx.x * 128 + tid;   // [0, 65536): (b, voxel)
    const int b  = gv >> 15;
    const int v  = gv & (G3 - 1);

    // ---- mask sum ----
    float msum = 0.f;
    #pragma unroll
    for (int n = 0; n < NVIEW; ++n) msum += __ldg(&mask[(b * NVIEW + n) * G3 + v]);
    const float minv = 1.f / (msum + EPS);
    const float ws   = msum * minv;

    // ================= phase 1: packed A1=Sum(w f), A2=Sum(w f^2) =================
    float fsave[NVIEW][32];            // per-thread local cache of feats
    ull A1p[16], A2p[16];
    #pragma unroll
    for (int j = 0; j < 16; ++j) { A1p[j] = 0ull; A2p[j] = 0ull; }

    #pragma unroll 1
    for (int n = 0; n < NVIEW; ++n) {
        const int bn = b * NVIEW + n;
        const float i0 = __ldg(&vdir[(bn * 3 + 0) * G3 + v]);
        const float i1 = __ldg(&vdir[(bn * 3 + 1) * G3 + v]);
        const float i2 = __ldg(&vdir[(bn * 3 + 2) * G3 + v]);
        const float i3 = __ldg(&depth[bn * G3 + v]);
        const float wn = __ldg(&mask[bn * G3 + v]) * minv;
        const ull  wn2 = pk2(wn, wn);

        ull hp8[8];
        #pragma unroll
        for (int o = 0; o < 16; o += 2) {
            const float4 wa = *reinterpret_cast<const float4*>(&s_rw1[o * 4]);
            const float4 wb = *reinterpret_cast<const float4*>(&s_rw1[(o + 1) * 4]);
            const float ha = elu_f(s_rb1[o]     + wa.x * i0 + wa.y * i1 + wa.z * i2 + wa.w * i3);
            const float hb = elu_f(s_rb1[o + 1] + wb.x * i0 + wb.y * i1 + wb.z * i2 + wb.w * i3);
            hp8[o >> 1] = pk2(ha, hb);
        }

        const float* fbase = &features[(bn * 32) * G3 + v];
        #pragma unroll
        for (int j = 0; j < 16; ++j) {
            const float a = __ldg(&fbase[(2 * j) * G3])
                          + elu_f(s_rb2[2 * j] + pdot<8>(&s_rw2[(2 * j) * 16], hp8));
            const float c = __ldg(&fbase[(2 * j + 1) * G3])
                          + elu_f(s_rb2[2 * j + 1] + pdot<8>(&s_rw2[(2 * j + 1) * 16], hp8));
            fsave[n][2 * j]     = a;
            fsave[n][2 * j + 1] = c;
            const ull fp = pk2(a, c);
            A1p[j] = fma2(wn2, fp, A1p[j]);
            A2p[j] = fma2(wn2, mul2(fp, fp), A2p[j]);
        }
    }

    // mean/var packed: var = A2 - mean^2 (2 - ws)
    {
        const float nw = -(2.f - ws);
        const ull  nw2 = pk2(nw, nw);
        #pragma unroll
        for (int j = 0; j < 16; ++j) {
            const ull m = A1p[j];
            A2p[j] = fma2(mul2(m, m), nw2, A2p[j]);   // A1p = mean, A2p = var
        }
    }

    // ---- hbase[o] = bb1[o] + bw1[o,0:32].mean + bw1[o,32:64].var (local) ----
    float hbase[64];
    #pragma unroll 1
    for (int o = 0; o < 64; ++o) {
        const float* rm = &g_bw1[o * 96];
        hbase[o] = __ldg(&g_bb1[o]) + pdot<16>(rm, A1p) + pdot<16>(rm + 32, A2p);
    }

    // ================= phase 2: per-view MLPs; S, Up, Vvp =================
    ull Up[16], Vvp[16];
    float S = 0.f;
    #pragma unroll
    for (int j = 0; j < 16; ++j) { Up[j] = 0ull; Vvp[j] = 0ull; }

    #pragma unroll 1
    for (int n = 0; n < NVIEW; ++n) {
        const int bn = b * NVIEW + n;
        const float mval = __ldg(&mask[bn * G3 + v]);
        const float wn   = mval * minv;

        ull fp[16];
        #pragma unroll
        for (int j = 0; j < 16; ++j) fp[j] = pk2(fsave[n][2 * j], fsave[n][2 * j + 1]);

        // --- base: h = elu(hbase + bw1f.f) (64); xx = elu(bb2 + bw2.h) (32); 16-chunks ---
        float xx[32];
        #pragma unroll
        for (int j = 0; j < 32; ++j) xx[j] = s_bb2[j];

        #pragma unroll 1
        for (int oc = 0; oc < 4; ++oc) {
            const int o16 = oc * 16;
            ull hp[8];
            #pragma unroll
            for (int k = 0; k < 16; k += 2) {
                const float ha = elu_f(hbase[o16 + k]     + pdot<16>(&s_bw1f[(o16 + k) * 32], fp));
                const float hb = elu_f(hbase[o16 + k + 1] + pdot<16>(&s_bw1f[(o16 + k + 1) * 32], fp));
                hp[k >> 1] = pk2(ha, hb);
            }
            #pragma unroll
            for (int j = 0; j < 32; ++j)
                xx[j] += pdot<8>(&s_bw2[j * 64 + o16], hp);
        }
        ull xxp[16];
        #pragma unroll
        for (int j = 0; j < 16; ++j)
            xxp[j] = pk2(elu_f(xx[2 * j]), elu_f(xx[2 * j + 1]));

        // --- vis: hv_o = elu(vb1_o + wn*(vw1_o.xx))  [scalar wn folded into dot] ---
        ull hvp[16];
        #pragma unroll
        for (int o = 0; o < 32; o += 2) {
            const float a = elu_f(s_vb1[o]     + wn * pdot<16>(&s_vw1[o * 32], xxp));
            const float c = elu_f(s_vb1[o + 1] + wn * pdot<16>(&s_vw1[(o + 1) * 32], xxp));
            hvp[o >> 1] = pk2(a, c);
        }
        #pragma unroll
        for (int j = 0; j < 32; j += 2) {
            const float a = elu_f(s_vb2[j]     + pdot<16>(&s_vw2[j * 32], hvp));
            const float c = elu_f(s_vb2[j + 1] + pdot<16>(&s_vw2[(j + 1) * 32], hvp));
            xxp[j >> 1] = add2(xxp[j >> 1], pk2(a, c));       // x = x + x_res
        }
        const float va  = s_vb2[32] + pdot<16>(&s_vw2[32 * 32], hvp);
        const float vis = sigm_f(elu_f(va)) * mval;

        // --- vis2: s2 = v2b2 + Σ v2w2_o * elu(v2b1_o + vis*(v2w1_o.xx)) ---
        float s2 = v2b2;
        #pragma unroll
        for (int o = 0; o < 32; o += 2) {
            const float a = elu_f(s_v2b1[o]     + vis * pdot<16>(&s_v2w1[o * 32], xxp));
            const float c = elu_f(s_v2b1[o + 1] + vis * pdot<16>(&s_v2w1[(o + 1) * 32], xxp));
            s2 += s_v2w2[o] * a + s_v2w2[o + 1] * c;
        }
        const float vis2 = sigm_f(s2) * mval;

        S += vis2;
        const ull v2d = pk2(vis2, vis2);
        #pragma unroll
        for (int j = 0; j < 16; ++j) {
            Up[j]  = fma2(v2d, xxp[j], Up[j]);
            Vvp[j] = fma2(v2d, mul2(xxp[j], xxp[j]), Vvp[j]);
        }
    }

    // ================= second mean/var + stat head (packed) =================
    const float Sinv  = 1.f / (S + EPS);
    const float w2s   = S * Sinv;
    const float wmean = w2s * 0.125f;
    {
        const ull sd  = pk2(Sinv, Sinv);
        const float nw = -(2.f - w2s);
        const ull nw2 = pk2(nw, nw);
        #pragma unroll
        for (int j = 0; j < 16; ++j) {
            const ull m2 = mul2(Up[j], sd);
            Up[j]  = m2;                                        // mean2
            Vvp[j] = fma2(mul2(m2, m2), nw2, mul2(Vvp[j], sd)); // var2
        }
    }

    #pragma unroll 1
    for (int o = 0; o < 32; ++o) {
        const float* wr = &s_sw[o * 68];
        const float acc = s_sb[o] + pdot<16>(wr, Up) + pdot<16>(wr + 32, Vvp) + wr[64] * wmean;
        out[(b * 32 + o) * G3 + v] = elu_f(acc);
    }
}

extern "C" void kernel_launch(void* const* d_in, const int* in_sizes, int n_in,
                              void* d_out, int out_size) {
    (void)in_sizes; (void)n_in; (void)out_size;
    const float* features = (const float*)d_in[0];
    const float* mask     = (const float*)d_in[1];
    const float* depth    = (const float*)d_in[2];
    const float* vdir     = (const float*)d_in[3];
    const float* rde_w1   = (const float*)d_in[4];
    const float* rde_b1   = (const float*)d_in[5];
    const float* rde_w2   = (const float*)d_in[6];
    const float* rde_b2   = (const float*)d_in[7];
    const float* base_w1  = (const float*)d_in[8];
    const float* base_b1  = (const float*)d_in[9];
    const float* base_w2  = (const float*)d_in[10];
    const float* base_b2  = (const float*)d_in[11];
    const float* vis_w1   = (const float*)d_in[12];
    const float* vis_b1   = (const float*)d_in[13];
    const float* vis_w2   = (const float*)d_in[14];
    const float* vis_b2   = (const float*)d_in[15];
    const float* vis2_w1  = (const float*)d_in[16];
    const float* vis2_b1  = (const float*)d_in[17];
    const float* vis2_w2  = (const float*)d_in[18];
    const float* vis2_b2  = (const float*)d_in[19];
    const float* stat_w   = (const float*)d_in[20];
    const float* stat_b   = (const float*)d_in[21];
    float* out = (float*)d_out;

    ibr_agg_v11_kernel<<<512, 128>>>(
        features, mask, depth, vdir,
        rde_w1, rde_b1, rde_w2, rde_b2,
        base_w1, base_b1, base_w2, base_b2,
        vis_w1, vis_b1, vis_w2, vis_b2,
        vis2_w1, vis2_b1, vis2_w2, vis2_b2,
        stat_w, stat_b, out);
}

// round 17
// speedup vs baseline: 1.2788x; 1.2788x over previous
#include <cuda_runtime.h>
#include <math.h>

#define G3 32768
#define NVIEW 8

typedef unsigned long long ull;

__device__ __forceinline__ float elu_f(float x)  { return x > 0.f ? x : (__expf(x) - 1.f); }
__device__ __forceinline__ float sigm_f(float x) { return 1.f / (1.f + __expf(-x)); }

__device__ __forceinline__ ull pk2(float lo, float hi) {
    ull r; asm("mov.b64 %0, {%1, %2};" : "=l"(r) : "f"(lo), "f"(hi)); return r;
}
__device__ __forceinline__ float2 upk2(ull a) {
    float lo, hi; asm("mov.b64 {%0, %1}, %2;" : "=f"(lo), "=f"(hi) : "l"(a));
    return make_float2(lo, hi);
}
__device__ __forceinline__ ull fma2(ull a, ull b, ull c) {
    ull d; asm("fma.rn.f32x2 %0, %1, %2, %3;" : "=l"(d) : "l"(a), "l"(b), "l"(c)); return d;
}
__device__ __forceinline__ ull mul2(ull a, ull b) {
    ull d; asm("mul.rn.f32x2 %0, %1, %2;" : "=l"(d) : "l"(a), "l"(b)); return d;
}
__device__ __forceinline__ ull add2(ull a, ull b) {
    ull d; asm("add.rn.f32x2 %0, %1, %2;" : "=l"(d) : "l"(a), "l"(b)); return d;
}
__device__ __forceinline__ float hsum2(ull a) { float2 f = upk2(a); return f.x + f.y; }

// Packed dot over NP f32x2 pairs (NP even). wr must be 16B-aligned; weights are
// channel-contiguous so a 16B load yields two packed operands directly.
template<int NP>
__device__ __forceinline__ float pdot(const float* __restrict__ wr, const ull* __restrict__ xp) {
    ull a0 = 0ull, a1 = 0ull;
    #pragma unroll
    for (int k = 0; k < NP / 2; ++k) {
        const ulonglong2 w = *reinterpret_cast<const ulonglong2*>(wr + 4 * k);
        a0 = fma2(w.x, xp[2 * k], a0);
        a1 = fma2(w.y, xp[2 * k + 1], a1);
    }
    return hsum2(add2(a0, a1));
}

__global__ __launch_bounds__(128)
void ibr_agg_f32x2_kernel(
    const float* __restrict__ features,   // (B,N,32,G3)
    const float* __restrict__ mask,       // (B,N,1,G3)
    const float* __restrict__ depth,      // (B,N,1,G3)
    const float* __restrict__ vdir,       // (B,N,3,G3)
    const float* __restrict__ g_rw1, const float* __restrict__ g_rb1,   // (16,4),(16)
    const float* __restrict__ g_rw2, const float* __restrict__ g_rb2,   // (32,16),(32)
    const float* __restrict__ g_bw1, const float* __restrict__ g_bb1,   // (64,96),(64)
    const float* __restrict__ g_bw2, const float* __restrict__ g_bb2,   // (32,64),(32)
    const float* __restrict__ g_vw1, const float* __restrict__ g_vb1,   // (32,32),(32)
    const float* __restrict__ g_vw2, const float* __restrict__ g_vb2,   // (33,32),(33)
    const float* __restrict__ g_v2w1, const float* __restrict__ g_v2b1, // (32,32),(32)
    const float* __restrict__ g_v2w2, const float* __restrict__ g_v2b2, // (1,32),(1)
    const float* __restrict__ g_sw,  const float* __restrict__ g_sb,    // (32,65),(32)
    float* __restrict__ out)              // (B,32,G3)
{
    __shared__ __align__(16) float s_rw1[16 * 4];
    __shared__ __align__(16) float s_rb1[16];
    __shared__ __align__(16) float s_rw2[32 * 16];
    __shared__ __align__(16) float s_rb2[32];
    __shared__ __align__(16) float s_bw1f[64 * 32];   // base_w1 cols 64..95 (feat part)
    __shared__ __align__(16) float s_bw2[32 * 64];
    __shared__ __align__(16) float s_bb2[32];
    __shared__ __align__(16) float s_vw1[32 * 32];
    __shared__ __align__(16) float s_vb1[32];
    __shared__ __align__(16) float s_vw2[33 * 32];
    __shared__ __align__(16) float s_vb2[36];
    __shared__ __align__(16) float s_v2w1[32 * 32];
    __shared__ __align__(16) float s_v2b1[32];
    __shared__ __align__(16) float s_v2w2[32];
    __shared__ __align__(16) float s_sw[32 * 68];     // stat_w rows padded 65->68
    __shared__ __align__(16) float s_sb[32];

    const int tid = threadIdx.x;

    for (int i = tid; i < 16 * 4;  i += 128) s_rw1[i] = g_rw1[i];
    if (tid < 16) s_rb1[tid] = g_rb1[tid];
    for (int i = tid; i < 32 * 16; i += 128) s_rw2[i] = g_rw2[i];
    if (tid < 32) s_rb2[tid] = g_rb2[tid];
    for (int i = tid; i < 64 * 32; i += 128) { int o = i >> 5, c = i & 31; s_bw1f[i] = g_bw1[o * 96 + 64 + c]; }
    for (int i = tid; i < 32 * 64; i += 128) s_bw2[i] = g_bw2[i];
    if (tid < 32) s_bb2[tid] = g_bb2[tid];
    for (int i = tid; i < 32 * 32; i += 128) s_vw1[i] = g_vw1[i];
    if (tid < 32) s_vb1[tid] = g_vb1[tid];
    for (int i = tid; i < 33 * 32; i += 128) s_vw2[i] = g_vw2[i];
    if (tid < 33) s_vb2[tid] = g_vb2[tid];
    for (int i = tid; i < 32 * 32; i += 128) s_v2w1[i] = g_v2w1[i];
    if (tid < 32) s_v2b1[tid] = g_v2b1[tid];
    if (tid < 32) s_v2w2[tid] = g_v2w2[tid];
    for (int i = tid; i < 32 * 65; i += 128) { int o = i / 65, c = i % 65; s_sw[o * 68 + c] = g_sw[i]; }
    if (tid < 32) s_sb[tid] = g_sb[tid];
    __syncthreads();

    const float EPS  = 1e-8f;
    const float v2b2 = __ldg(g_v2b2);

    const int gv = blockIdx.x * 128 + tid;   // [0, 65536): (b, voxel)
    const int b  = gv >> 15;
    const int v  = gv & (G3 - 1);

    // ---- mask sum ----
    float msum = 0.f;
    #pragma unroll
    for (int n = 0; n < NVIEW; ++n) msum += __ldg(&mask[(b * NVIEW + n) * G3 + v]);
    const float minv = 1.f / (msum + EPS);
    const float ws   = msum * minv;

    // ================= phase 1: packed A1=Sum(w f), A2=Sum(w f^2) =================
    float fsave[NVIEW][32];            // per-thread local cache of feats
    ull A1p[16], A2p[16];
    #pragma unroll
    for (int j = 0; j < 16; ++j) { A1p[j] = 0ull; A2p[j] = 0ull; }

    #pragma unroll 1
    for (int n = 0; n < NVIEW; ++n) {
        const int bn = b * NVIEW + n;
        const float i0 = __ldg(&vdir[(bn * 3 + 0) * G3 + v]);
        const float i1 = __ldg(&vdir[(bn * 3 + 1) * G3 + v]);
        const float i2 = __ldg(&vdir[(bn * 3 + 2) * G3 + v]);
        const float i3 = __ldg(&depth[bn * G3 + v]);
        const float wn = __ldg(&mask[bn * G3 + v]) * minv;
        const ull  wn2 = pk2(wn, wn);

        ull hp8[8];
        #pragma unroll
        for (int o = 0; o < 16; o += 2) {
            const float4 wa = *reinterpret_cast<const float4*>(&s_rw1[o * 4]);
            const float4 wb = *reinterpret_cast<const float4*>(&s_rw1[(o + 1) * 4]);
            const float ha = elu_f(s_rb1[o]     + wa.x * i0 + wa.y * i1 + wa.z * i2 + wa.w * i3);
            const float hb = elu_f(s_rb1[o + 1] + wb.x * i0 + wb.y * i1 + wb.z * i2 + wb.w * i3);
            hp8[o >> 1] = pk2(ha, hb);
        }

        float fv[32];
        const float* fbase = &features[(bn * 32) * G3 + v];
        #pragma unroll
        for (int c = 0; c < 32; ++c) {
            const float acc = pdot<8>(&s_rw2[c * 16], hp8);
            fv[c] = __ldg(&fbase[c * G3]) + elu_f(s_rb2[c] + acc);
            fsave[n][c] = fv[c];
        }
        #pragma unroll
        for (int j = 0; j < 16; ++j) {
            const ull fp = pk2(fv[2 * j], fv[2 * j + 1]);
            A1p[j] = fma2(wn2, fp, A1p[j]);
            A2p[j] = fma2(wn2, mul2(fp, fp), A2p[j]);
        }
    }

    // mean/var packed: var = A2 - mean^2 (2 - ws)
    {
        const float nw = -(2.f - ws);
        const ull  nw2 = pk2(nw, nw);
        #pragma unroll
        for (int j = 0; j < 16; ++j) {
            const ull m = A1p[j];
            A2p[j] = fma2(mul2(m, m), nw2, A2p[j]);   // A1p = mean, A2p = var
        }
    }

    // ---- hbase[o] = bb1[o] + bw1[o,0:32].mean + bw1[o,32:64].var (packed dots) ----
    float hbase[64];   // local; re-read per view in phase 2
    #pragma unroll 1
    for (int o = 0; o < 64; ++o) {
        const float* rm = &g_bw1[o * 96];
        hbase[o] = __ldg(&g_bb1[o]) + pdot<16>(rm, A1p) + pdot<16>(rm + 32, A2p);
    }

    // ================= phase 2: per-view MLPs; S, Up=Sum(vis2 x), Vvp=Sum(vis2 x^2) =====
    ull Up[16], Vvp[16];
    float S = 0.f;
    #pragma unroll
    for (int j = 0; j < 16; ++j) { Up[j] = 0ull; Vvp[j] = 0ull; }

    #pragma unroll 1
    for (int n = 0; n < NVIEW; ++n) {
        const int bn = b * NVIEW + n;
        const float mval = __ldg(&mask[bn * G3 + v]);
        const float wn   = mval * minv;

        ull fp[16];
        #pragma unroll
        for (int j = 0; j < 16; ++j) fp[j] = pk2(fsave[n][2 * j], fsave[n][2 * j + 1]);

        // --- base: h = elu(hbase + bw1f.f) (64); xx = elu(bb2 + bw2.h) (32); 16-chunks ---
        float xx[32];
        #pragma unroll
        for (int j = 0; j < 32; ++j) xx[j] = s_bb2[j];

        #pragma unroll 1
        for (int oc = 0; oc < 4; ++oc) {
            const int o16 = oc * 16;
            ull hp[8];
            #pragma unroll
            for (int k = 0; k < 16; k += 2) {
                const float ha = elu_f(hbase[o16 + k]     + pdot<16>(&s_bw1f[(o16 + k) * 32], fp));
                const float hb = elu_f(hbase[o16 + k + 1] + pdot<16>(&s_bw1f[(o16 + k + 1) * 32], fp));
                hp[k >> 1] = pk2(ha, hb);
            }
            #pragma unroll
            for (int j = 0; j < 32; ++j)
                xx[j] += pdot<8>(&s_bw2[j * 64 + o16], hp);
        }
        ull xxp[16];
        #pragma unroll
        for (int j = 0; j < 16; ++j)
            xxp[j] = pk2(elu_f(xx[2 * j]), elu_f(xx[2 * j + 1]));

        // --- vis: t = xx*wn ; hv = elu(vw1.t) ; xx += elu(vb2 + vw2.hv) ; va ---
        const ull wn2 = pk2(wn, wn);
        ull tp[16];
        #pragma unroll
        for (int j = 0; j < 16; ++j) tp[j] = mul2(xxp[j], wn2);

        ull hvp[16];
        #pragma unroll
        for (int o = 0; o < 32; o += 2) {
            const float a = elu_f(s_vb1[o]     + pdot<16>(&s_vw1[o * 32], tp));
            const float c = elu_f(s_vb1[o + 1] + pdot<16>(&s_vw1[(o + 1) * 32], tp));
            hvp[o >> 1] = pk2(a, c);
        }

        #pragma unroll
        for (int j = 0; j < 32; j += 2) {
            const float a = elu_f(s_vb2[j]     + pdot<16>(&s_vw2[j * 32], hvp));
            const float c = elu_f(s_vb2[j + 1] + pdot<16>(&s_vw2[(j + 1) * 32], hvp));
            xxp[j >> 1] = add2(xxp[j >> 1], pk2(a, c));       // x = x + x_res
        }
        const float va  = s_vb2[32] + pdot<16>(&s_vw2[32 * 32], hvp);
        const float vis = sigm_f(elu_f(va)) * mval;

        // --- vis2: t2 = xx*vis ; s2 = v2b2 + v2w2.elu(v2w1.t2) ---
        const ull visd = pk2(vis, vis);
        #pragma unroll
        for (int j = 0; j < 16; ++j) tp[j] = mul2(xxp[j], visd);

        float s2 = v2b2;
        #pragma unroll
        for (int o = 0; o < 32; o += 2) {
            const float a = elu_f(s_v2b1[o]     + pdot<16>(&s_v2w1[o * 32], tp));
            const float c = elu_f(s_v2b1[o + 1] + pdot<16>(&s_v2w1[(o + 1) * 32], tp));
            s2 += s_v2w2[o] * a + s_v2w2[o + 1] * c;
        }
        const float vis2 = sigm_f(s2) * mval;

        S += vis2;
        const ull v2d = pk2(vis2, vis2);
        #pragma unroll
        for (int j = 0; j < 16; ++j) {
            Up[j]  = fma2(v2d, xxp[j], Up[j]);
            Vvp[j] = fma2(v2d, mul2(xxp[j], xxp[j]), Vvp[j]);
        }
    }

    // ================= second mean/var + stat head (packed) =================
    const float Sinv  = 1.f / (S + EPS);
    const float w2s   = S * Sinv;
    const float wmean = w2s * 0.125f;
    {
        const ull sd  = pk2(Sinv, Sinv);
        const float nw = -(2.f - w2s);
        const ull nw2 = pk2(nw, nw);
        #pragma unroll
        for (int j = 0; j < 16; ++j) {
            const ull m2 = mul2(Up[j], sd);
            Up[j]  = m2;                                        // mean2
            Vvp[j] = fma2(mul2(m2, m2), nw2, mul2(Vvp[j], sd)); // var2
        }
    }

    #pragma unroll 1
    for (int o = 0; o < 32; ++o) {
        const float* wr = &s_sw[o * 68];
        float acc = s_sb[o] + pdot<16>(wr, Up) + pdot<16>(wr + 32, Vvp) + wr[64] * wmean;
        out[(b * 32 + o) * G3 + v] = elu_f(acc);
    }
}

extern "C" void kernel_launch(void* const* d_in, const int* in_sizes, int n_in,
                              void* d_out, int out_size) {
    (void)in_sizes; (void)n_in; (void)out_size;
    const float* features = (const float*)d_in[0];
    const float* mask     = (const float*)d_in[1];
    const float* depth    = (const float*)d_in[2];
    const float* vdir     = (const float*)d_in[3];
    const float* rde_w1   = (const float*)d_in[4];
    const float* rde_b1   = (const float*)d_in[5];
    const float* rde_w2   = (const float*)d_in[6];
    const float* rde_b2   = (const float*)d_in[7];
    const float* base_w1  = (const float*)d_in[8];
    const float* base_b1  = (const float*)d_in[9];
    const float* base_w2  = (const float*)d_in[10];
    const float* base_b2  = (const float*)d_in[11];
    const float* vis_w1   = (const float*)d_in[12];
    const float* vis_b1   = (const float*)d_in[13];
    const float* vis_w2   = (const float*)d_in[14];
    const float* vis_b2   = (const float*)d_in[15];
    const float* vis2_w1  = (const float*)d_in[16];
    const float* vis2_b1  = (const float*)d_in[17];
    const float* vis2_w2  = (const float*)d_in[18];
    const float* vis2_b2  = (const float*)d_in[19];
    const float* stat_w   = (const float*)d_in[20];
    const float* stat_b   = (const float*)d_in[21];
    float* out = (float*)d_out;

    ibr_agg_f32x2_kernel<<<512, 128>>>(
        features, mask, depth, vdir,
        rde_w1, rde_b1, rde_w2, rde_b2,
        base_w1, base_b1, base_w2, base_b2,
        vis_w1, vis_b1, vis_w2, vis_b2,
        vis2_w1, vis2_b1, vis2_w2, vis2_b2,
        stat_w, stat_b, out);
}